// round 10
// baseline (speedup 1.0000x reference)
#include <cuda_runtime.h>
#include <cuda_fp16.h>
#include <mma.h>

using namespace nvcuda;

// Problem constants
#define NTOK   131072          // B*S = 32*4096
#define DIM    1024
#define BATCH  32
#define SEQ    4096
#define NBLOCKS ((NTOK/128)*(DIM/256))  // 4096

// ---------------- device scratch ----------------
__device__ __half g_A  [1024*1024];            // logits weights: wq_h @ kv_h^T  [d][hr]
__device__ __half g_Bm [1024*1024];            // kv_h @ wo_h                   [hr][d]
__device__ __half g_w1h[1024*1024];            // w1 [k][n]
__device__ __half g_w2h[1024*1024];            // w2 [k][n]
__device__ __half g_Xh [(size_t)NTOK*1024];    // x in fp16     (256MB)
__device__ __half g_P  [(size_t)NTOK*1024];    // softmax probs (256MB)
__device__ __half g_U  [(size_t)NTOK*1024];    // out@wo        (256MB)
__device__ __half g_H  [(size_t)NTOK*1024];    // gelu hidden   (256MB)

// ---------------- helpers ----------------
__global__ void zero_out_kernel(float* o, int n) {
    int i = blockIdx.x * 256 + threadIdx.x;
    if (i < n) o[i] = 0.0f;
}

// A[d, h*64+r] = sum_j wq[d, h*64+j] * kv[r, h*64+j]
__global__ void prep_A_kernel(const float* __restrict__ wq,
                              const float* __restrict__ kv) {
    __shared__ float wq_s[64][65];
    __shared__ float kv_s[64][65];
    int h  = blockIdx.x;
    int dt = blockIdx.y;
    int t  = threadIdx.x;
    #pragma unroll
    for (int e = 0; e < 16; e++) {
        int lin = t + 256 * e;
        int r = lin >> 6, c = lin & 63;
        wq_s[r][c] = wq[(size_t)(dt*64 + r)*1024 + h*64 + c];
        kv_s[r][c] = kv[(size_t)r*1024 + h*64 + c];
    }
    __syncthreads();
    #pragma unroll
    for (int e = 0; e < 16; e++) {
        int lin = t + 256 * e;
        int i = lin >> 6, r = lin & 63;
        float s = 0.f;
        #pragma unroll
        for (int j = 0; j < 64; j++) s += wq_s[i][j] * kv_s[r][j];
        g_A[(size_t)(dt*64 + i)*1024 + h*64 + r] = __float2half_rn(s);
    }
}

// Bm[h*64+r, d] = sum_j kv[r, h*64+j] * wo[h*64+j, d]
__global__ void prep_B_kernel(const float* __restrict__ kv,
                              const float* __restrict__ wo) {
    __shared__ float kv_s[64][65];
    __shared__ float wo_s[64][65];
    int h  = blockIdx.x;
    int ct = blockIdx.y;
    int t  = threadIdx.x;
    #pragma unroll
    for (int e = 0; e < 16; e++) {
        int lin = t + 256 * e;
        int r = lin >> 6, c = lin & 63;
        kv_s[r][c] = kv[(size_t)r*1024 + h*64 + c];
        wo_s[r][c] = wo[(size_t)(h*64 + r)*1024 + ct*64 + c];
    }
    __syncthreads();
    #pragma unroll
    for (int e = 0; e < 16; e++) {
        int lin = t + 256 * e;
        int r = lin >> 6, d = lin & 63;
        float s = 0.f;
        #pragma unroll
        for (int j = 0; j < 64; j++) s += kv_s[r][j] * wo_s[j][d];
        g_Bm[(size_t)(h*64 + r)*1024 + ct*64 + d] = __float2half_rn(s);
    }
}

__global__ void conv_w_kernel(const float* __restrict__ w1,
                              const float* __restrict__ w2) {
    int i = blockIdx.x * 256 + threadIdx.x;
    g_w1h[i] = __float2half_rn(w1[i]);
    g_w2h[i] = __float2half_rn(w2[i]);
}

// convert x (fp32 -> fp16), 8 elems per thread
__global__ void conv_x_kernel(const float* __restrict__ x) {
    size_t i = ((size_t)blockIdx.x * 256 + threadIdx.x) * 8;
    float4 a = *(const float4*)(x + i);
    float4 b = *(const float4*)(x + i + 4);
    union { uint4 u4; __half2 h2[4]; } pk;
    pk.h2[0] = __floats2half2_rn(a.x, a.y);
    pk.h2[1] = __floats2half2_rn(a.z, a.w);
    pk.h2[2] = __floats2half2_rn(b.x, b.y);
    pk.h2[3] = __floats2half2_rn(b.z, b.w);
    *(uint4*)(g_Xh + i) = pk.u4;
}

__device__ __forceinline__ void cpa16(void* dst, const void* src) {
    unsigned s = (unsigned)__cvta_generic_to_shared(dst);
    asm volatile("cp.async.cg.shared.global [%0], [%1], 16;\n" :: "r"(s), "l"(src));
}

// ---- fused GEMM: 128x256 tile, 512 threads, K-chunk 128, 2-stage cp.async ---
// Stage = {A[128x136] halves (34816 B), W[128x264] halves (67584 B)} = 102400 B.
// 2 stages = 204800 B (1 CTA/SM). 8 chunks -> 8 barrier events per tile.
// Epilogue reuses smem as C_s float[128][260] = 133120 B.
// Warp grid: 4 row groups of 32 (wm) x 4 col groups of 64 (wn).
#define A_BYTES     34816
#define STAGE_BYTES 102400
#define SMEM_BYTES  (2*STAGE_BYTES)

template<int MODE>
__global__ void __launch_bounds__(512)
fused_gemm(const float* __restrict__ bias, float* __restrict__ outp) {
    extern __shared__ char smem[];
    float* C_s = (float*)smem;     // 128 x 260 floats (reuse)

    const __half* Ag;
    const __half* Wg;
    if constexpr (MODE == 0)      { Ag = g_Xh; Wg = g_A;   }
    else if constexpr (MODE == 1) { Ag = g_P;  Wg = g_Bm;  }
    else if constexpr (MODE == 2) { Ag = g_U;  Wg = g_w1h; }
    else                          { Ag = g_H;  Wg = g_w2h; }

    int t    = threadIdx.x;
    int bid  = blockIdx.x;
    int rt   = bid >> 2;       // 1024 row tiles
    int ct   = bid & 3;        // 4 col tiles of 256
    int row0 = rt * 128;
    int n0   = ct * 256;
    int warp = t >> 5;
    int wm   = warp & 3;       // 4 warp rows of 32
    int wn   = warp >> 2;      // 4 warp cols of 64

    wmma::fragment<wmma::accumulator, 16, 16, 16, float> acc[2][4];
    #pragma unroll
    for (int mi = 0; mi < 2; mi++)
        #pragma unroll
        for (int ni = 0; ni < 4; ni++)
            wmma::fill_fragment(acc[mi][ni], 0.0f);

    // stage one 128-wide K chunk into buffer `buf` (512 threads)
    auto stage = [&](int kc, int buf) {
        __half* A_s = (__half*)(smem + buf*STAGE_BYTES);
        __half* W_s = (__half*)(smem + buf*STAGE_BYTES + A_BYTES);
        #pragma unroll
        for (int e = 0; e < 4; e++) {            // A: 128 x 128 (2048 x 16B)
            int lin = t + 512*e;
            int r = lin >> 4, sg = lin & 15;
            cpa16(A_s + r*136 + sg*8, Ag + (size_t)(row0 + r)*1024 + kc + sg*8);
        }
        #pragma unroll
        for (int e = 0; e < 8; e++) {            // W: 128 x 256 (4096 x 16B)
            int lin = t + 512*e;
            int r = lin >> 5, sg = lin & 31;
            cpa16(W_s + r*264 + sg*8, Wg + (size_t)(kc + r)*1024 + n0 + sg*8);
        }
        asm volatile("cp.async.commit_group;\n");
    };

    // prologue: chunk 0
    stage(0, 0);

    for (int k = 0; k < 8; k++) {
        asm volatile("cp.async.wait_group 0;\n");   // chunk k fully arrived
        __syncthreads();   // visible block-wide; all reads of buf (k+1)&1 (iter k-1) done

        if (k + 1 < 8) stage((k+1)*128, (k+1) & 1);  // overlaps with compute below

        const __half* A_s = (const __half*)(smem + (k&1)*STAGE_BYTES);
        const __half* W_s = (const __half*)(smem + (k&1)*STAGE_BYTES + A_BYTES);
        #pragma unroll
        for (int kk = 0; kk < 128; kk += 16) {
            wmma::fragment<wmma::matrix_a, 16, 16, 16, __half, wmma::row_major> af[2];
            wmma::fragment<wmma::matrix_b, 16, 16, 16, __half, wmma::row_major> bf[4];
            #pragma unroll
            for (int mi = 0; mi < 2; mi++)
                wmma::load_matrix_sync(af[mi], A_s + (wm*32 + mi*16)*136 + kk, 136);
            #pragma unroll
            for (int ni = 0; ni < 4; ni++)
                wmma::load_matrix_sync(bf[ni], W_s + kk*264 + wn*64 + ni*16, 264);
            #pragma unroll
            for (int mi = 0; mi < 2; mi++)
                #pragma unroll
                for (int ni = 0; ni < 4; ni++)
                    wmma::mma_sync(acc[mi][ni], af[mi], bf[ni], acc[mi][ni]);
        }
    }
    __syncthreads();   // all smem reads done before C_s overwrite

    // ---- dump accumulators to SMEM ----
    #pragma unroll
    for (int mi = 0; mi < 2; mi++)
        #pragma unroll
        for (int ni = 0; ni < 4; ni++)
            wmma::store_matrix_sync(C_s + (wm*32 + mi*16)*260 + wn*64 + ni*16,
                                    acc[mi][ni], 260, wmma::mem_row_major);
    __syncthreads();

    // ---- epilogues (512 threads) ----
    if constexpr (MODE == 0) {
        const float scale = 0.125f;                 // R^-0.5
        int row  = t >> 2;                          // 128 rows
        int head = t & 3;                           // 4 head blocks of 64
        const float* rowp = C_s + row*260 + head*64;
        float m = -1e30f;
        #pragma unroll
        for (int j = 0; j < 64; j++) m = fmaxf(m, rowp[j] * scale);
        float s = 0.f;
        #pragma unroll
        for (int j = 0; j < 64; j++) s += __expf(rowp[j]*scale - m);
        float inv = 1.f / s;
        __half* op = g_P + (size_t)(row0 + row)*1024 + n0 + head*64;
        #pragma unroll
        for (int j = 0; j < 64; j += 8) {
            union { uint4 u4; __half2 h2[4]; } pk;
            #pragma unroll
            for (int q = 0; q < 4; q++) {
                float v0 = __expf(rowp[j + 2*q    ]*scale - m) * inv;
                float v1 = __expf(rowp[j + 2*q + 1]*scale - m) * inv;
                pk.h2[q] = __floats2half2_rn(v0, v1);
            }
            *(uint4*)(op + j) = pk.u4;
        }
    } else if constexpr (MODE == 1 || MODE == 2) {
        __half* dstbase = (MODE == 1) ? g_U : g_H;
        #pragma unroll
        for (int v = 0; v < 8; v++) {
            int lin = t + 512 * v;
            int i = lin >> 5, u = lin & 31;
            const float* src = C_s + i*260 + u*8;
            float vals[8];
            #pragma unroll
            for (int jj = 0; jj < 8; jj++) vals[jj] = src[jj];
            if constexpr (MODE == 2) {
                #pragma unroll
                for (int jj = 0; jj < 8; jj++) {
                    float z = vals[jj] + __ldg(bias + n0 + u*8 + jj);
                    vals[jj] = 0.5f * z * (1.0f + erff(z * 0.70710678118f));
                }
            }
            union { uint4 u4; __half2 h2[4]; } pk;
            #pragma unroll
            for (int q = 0; q < 4; q++)
                pk.h2[q] = __floats2half2_rn(vals[2*q], vals[2*q+1]);
            *(uint4*)(dstbase + (size_t)(row0 + i)*1024 + n0 + u*8) = pk.u4;
        }
    } else {
        // MODE 3: y = C + b2 + U residual; 512 threads = 256 cols x 2 row halves
        {
            int gcol = n0 + (t & 255);
            int half = t >> 8;                      // 0 or 1 -> rows 0-63 / 64-127
            float b2v = __ldg(bias + gcol);
            float s = 0.f;
            int i0 = half*64;
            #pragma unroll 4
            for (int i = i0; i < i0 + 64; i++) {
                float u = __half2float(g_U[(size_t)(row0 + i)*1024 + gcol]);
                s += C_s[i*260 + (t & 255)] + b2v + u;
            }
            int b = row0 >> 12;
            atomicAdd(outp + b*1024 + gcol, s * (1.0f/4096.0f));
        }
    }
}

// ---------------- launch ----------------
extern "C" void kernel_launch(void* const* d_in, const int* in_sizes, int n_in,
                              void* d_out, int out_size) {
    const float* x  = (const float*)d_in[0];
    const float* wq = (const float*)d_in[1];
    const float* kv = (const float*)d_in[2];
    const float* wo = (const float*)d_in[3];
    const float* w1 = (const float*)d_in[4];
    const float* b1 = (const float*)d_in[5];
    const float* w2 = (const float*)d_in[6];
    const float* b2 = (const float*)d_in[7];
    float* out = (float*)d_out;

    cudaFuncSetAttribute(fused_gemm<0>, cudaFuncAttributeMaxDynamicSharedMemorySize, SMEM_BYTES);
    cudaFuncSetAttribute(fused_gemm<1>, cudaFuncAttributeMaxDynamicSharedMemorySize, SMEM_BYTES);
    cudaFuncSetAttribute(fused_gemm<2>, cudaFuncAttributeMaxDynamicSharedMemorySize, SMEM_BYTES);
    cudaFuncSetAttribute(fused_gemm<3>, cudaFuncAttributeMaxDynamicSharedMemorySize, SMEM_BYTES);

    // order: 4th launch is what ncu captures -> keep the GEMM there
    conv_x_kernel<<<65536, 256>>>(x);                              // 1
    prep_A_kernel<<<dim3(16, 16), 256>>>(wq, kv);                  // 2
    prep_B_kernel<<<dim3(16, 16), 256>>>(kv, wo);                  // 3
    fused_gemm<0><<<NBLOCKS, 512, SMEM_BYTES>>>(nullptr, nullptr); // 4 <- profiled
    conv_w_kernel<<<4096, 256>>>(w1, w2);                          // 5
    zero_out_kernel<<<128, 256>>>(out, BATCH * DIM);               // 6
    fused_gemm<1><<<NBLOCKS, 512, SMEM_BYTES>>>(nullptr, nullptr); // 7
    fused_gemm<2><<<NBLOCKS, 512, SMEM_BYTES>>>(b1,      nullptr); // 8
    fused_gemm<3><<<NBLOCKS, 512, SMEM_BYTES>>>(b2,      out);     // 9
}

// round 11
// speedup vs baseline: 1.0396x; 1.0396x over previous
#include <cuda_runtime.h>
#include <cuda_fp16.h>
#include <cstdint>

// Problem constants
#define NTOK   131072          // B*S = 32*4096
#define DIM    1024
#define BATCH  32
#define SEQ    4096
#define NBLOCKS ((NTOK/128)*(DIM/256))  // 4096

// ---------------- device scratch ----------------
__device__ __half g_A  [1024*1024];            // logits weights: wq_h @ kv_h^T  [d][hr]
__device__ __half g_Bm [1024*1024];            // kv_h @ wo_h                   [hr][d]
__device__ __half g_w1h[1024*1024];            // w1 [k][n]
__device__ __half g_w2h[1024*1024];            // w2 [k][n]
__device__ __half g_Xh [(size_t)NTOK*1024];    // x in fp16     (256MB)
__device__ __half g_P  [(size_t)NTOK*1024];    // softmax probs (256MB)
__device__ __half g_U  [(size_t)NTOK*1024];    // out@wo        (256MB)
__device__ __half g_H  [(size_t)NTOK*1024];    // gelu hidden   (256MB)

// ---------------- helpers ----------------
__device__ __forceinline__ uint32_t s2u(const void* p) {
    uint32_t a;
    asm("{ .reg .u64 t; cvta.to.shared.u64 t, %1; cvt.u32.u64 %0, t; }" : "=r"(a) : "l"(p));
    return a;
}
__device__ __forceinline__ void cpa16(void* dst, const void* src) {
    unsigned s = (unsigned)__cvta_generic_to_shared(dst);
    asm volatile("cp.async.cg.shared.global [%0], [%1], 16;\n" :: "r"(s), "l"(src));
}
#define LDM4(r, addr) \
    asm volatile("ldmatrix.sync.aligned.m8n8.x4.shared.b16 {%0,%1,%2,%3}, [%4];" \
        : "=r"((r)[0]), "=r"((r)[1]), "=r"((r)[2]), "=r"((r)[3]) : "r"(addr))
#define LDM4T(r, addr) \
    asm volatile("ldmatrix.sync.aligned.m8n8.x4.trans.shared.b16 {%0,%1,%2,%3}, [%4];" \
        : "=r"((r)[0]), "=r"((r)[1]), "=r"((r)[2]), "=r"((r)[3]) : "r"(addr))
#define MMA16816(d, a, b0v, b1v) \
    asm volatile("mma.sync.aligned.m16n8k16.row.col.f32.f16.f16.f32 " \
        "{%0,%1,%2,%3}, {%4,%5,%6,%7}, {%8,%9}, {%0,%1,%2,%3};" \
        : "+f"((d)[0]), "+f"((d)[1]), "+f"((d)[2]), "+f"((d)[3]) \
        : "r"((a)[0]), "r"((a)[1]), "r"((a)[2]), "r"((a)[3]), "r"(b0v), "r"(b1v))

// ---------------- prep kernels (unchanged, hardware-validated) ----------------
__global__ void zero_out_kernel(float* o, int n) {
    int i = blockIdx.x * 256 + threadIdx.x;
    if (i < n) o[i] = 0.0f;
}

__global__ void prep_A_kernel(const float* __restrict__ wq,
                              const float* __restrict__ kv) {
    __shared__ float wq_s[64][65];
    __shared__ float kv_s[64][65];
    int h  = blockIdx.x;
    int dt = blockIdx.y;
    int t  = threadIdx.x;
    #pragma unroll
    for (int e = 0; e < 16; e++) {
        int lin = t + 256 * e;
        int r = lin >> 6, c = lin & 63;
        wq_s[r][c] = wq[(size_t)(dt*64 + r)*1024 + h*64 + c];
        kv_s[r][c] = kv[(size_t)r*1024 + h*64 + c];
    }
    __syncthreads();
    #pragma unroll
    for (int e = 0; e < 16; e++) {
        int lin = t + 256 * e;
        int i = lin >> 6, r = lin & 63;
        float s = 0.f;
        #pragma unroll
        for (int j = 0; j < 64; j++) s += wq_s[i][j] * kv_s[r][j];
        g_A[(size_t)(dt*64 + i)*1024 + h*64 + r] = __float2half_rn(s);
    }
}

__global__ void prep_B_kernel(const float* __restrict__ kv,
                              const float* __restrict__ wo) {
    __shared__ float kv_s[64][65];
    __shared__ float wo_s[64][65];
    int h  = blockIdx.x;
    int ct = blockIdx.y;
    int t  = threadIdx.x;
    #pragma unroll
    for (int e = 0; e < 16; e++) {
        int lin = t + 256 * e;
        int r = lin >> 6, c = lin & 63;
        kv_s[r][c] = kv[(size_t)r*1024 + h*64 + c];
        wo_s[r][c] = wo[(size_t)(h*64 + r)*1024 + ct*64 + c];
    }
    __syncthreads();
    #pragma unroll
    for (int e = 0; e < 16; e++) {
        int lin = t + 256 * e;
        int r = lin >> 6, d = lin & 63;
        float s = 0.f;
        #pragma unroll
        for (int j = 0; j < 64; j++) s += kv_s[r][j] * wo_s[j][d];
        g_Bm[(size_t)(h*64 + r)*1024 + ct*64 + d] = __float2half_rn(s);
    }
}

__global__ void conv_w_kernel(const float* __restrict__ w1,
                              const float* __restrict__ w2) {
    int i = blockIdx.x * 256 + threadIdx.x;
    g_w1h[i] = __float2half_rn(w1[i]);
    g_w2h[i] = __float2half_rn(w2[i]);
}

__global__ void conv_x_kernel(const float* __restrict__ x) {
    size_t i = ((size_t)blockIdx.x * 256 + threadIdx.x) * 8;
    float4 a = *(const float4*)(x + i);
    float4 b = *(const float4*)(x + i + 4);
    union { uint4 u4; __half2 h2[4]; } pk;
    pk.h2[0] = __floats2half2_rn(a.x, a.y);
    pk.h2[1] = __floats2half2_rn(a.z, a.w);
    pk.h2[2] = __floats2half2_rn(b.x, b.y);
    pk.h2[3] = __floats2half2_rn(b.z, b.w);
    *(uint4*)(g_Xh + i) = pk.u4;
}

// ---- fused GEMM: 128x256 tile, 512 threads, chunk 64, 3-stage cp.async,
// ---- raw ldmatrix + mma.sync.m16n8k16 inner loop.
// Stage = {A[128x72] halves (18432 B), W[64x264] halves (33792 B)} = 52224 B.
// A row pitch 144 B (=16 mod 128 -> ldmatrix conflict-free),
// W row pitch 528 B (=16 mod 128 -> conflict-free, incl. trans loads).
// Warp grid: 4 row groups of 32 (wm) x 4 col groups of 64 (wn).
#define A_BYTES     18432
#define STAGE_BYTES 52224
#define SMEM_BYTES  (3*STAGE_BYTES)

template<int MODE>
__global__ void __launch_bounds__(512)
fused_gemm(const float* __restrict__ bias, float* __restrict__ outp) {
    extern __shared__ char smem[];
    uint32_t sbase = s2u(smem);
    float* C_s = (float*)smem;     // 128 x 260 floats (reuse)

    const __half* Ag;
    const __half* Wg;
    if constexpr (MODE == 0)      { Ag = g_Xh; Wg = g_A;   }
    else if constexpr (MODE == 1) { Ag = g_P;  Wg = g_Bm;  }
    else if constexpr (MODE == 2) { Ag = g_U;  Wg = g_w1h; }
    else                          { Ag = g_H;  Wg = g_w2h; }

    int t    = threadIdx.x;
    int bid  = blockIdx.x;
    int rt   = bid >> 2;       // 1024 row tiles
    int ct   = bid & 3;        // 4 col tiles of 256
    int row0 = rt * 128;
    int n0   = ct * 256;
    int warp = t >> 5;
    int lane = t & 31;
    int wm   = warp & 3;       // 4 warp rows of 32
    int wn   = warp >> 2;      // 4 warp cols of 64

    // fragment lane addressing
    int lr = lane & 15, lh = lane >> 4;       // A: row lr, k-half lh
    int q  = lane >> 3;                       // B: quad 0..3
    int qk = (q & 1) * 8;                     //   k-half row offset
    int qn = (q >> 1) * 8;                    //   n-half (halves)

    float acc[2][8][4];
    #pragma unroll
    for (int mi = 0; mi < 2; mi++)
        #pragma unroll
        for (int j = 0; j < 8; j++)
            #pragma unroll
            for (int c = 0; c < 4; c++) acc[mi][j][c] = 0.f;

    // stage one 64-wide K chunk into buffer `buf` (512 threads)
    auto stage = [&](int kc, int buf) {
        __half* A_s = (__half*)(smem + buf*STAGE_BYTES);
        __half* W_s = (__half*)(smem + buf*STAGE_BYTES + A_BYTES);
        #pragma unroll
        for (int e = 0; e < 2; e++) {            // A: 128 x 64 (1024 x 16B)
            int lin = t + 512*e;
            int r = lin >> 3, sg = lin & 7;
            cpa16(A_s + r*72 + sg*8, Ag + (size_t)(row0 + r)*1024 + kc + sg*8);
        }
        #pragma unroll
        for (int e = 0; e < 4; e++) {            // W: 64 x 256 (2048 x 16B)
            int lin = t + 512*e;
            int r = lin >> 5, sg = lin & 31;
            cpa16(W_s + r*264 + sg*8, Wg + (size_t)(kc + r)*1024 + n0 + sg*8);
        }
        asm volatile("cp.async.commit_group;\n");
    };

    // prologue: chunks 0 and 1
    stage(0, 0);
    stage(64, 1);

    for (int k = 0; k < 16; k++) {
        if (k < 15) asm volatile("cp.async.wait_group 1;\n");
        else        asm volatile("cp.async.wait_group 0;\n");
        __syncthreads();   // chunk k visible block-wide; slot (k+2)%3 readers (iter k-1) done

        if (k + 2 < 16) stage((k+2)*64, (k+2) % 3);

        int slot = k - (k/3)*3;
        uint32_t A_u = sbase + slot*STAGE_BYTES;
        uint32_t W_u = A_u + A_BYTES;
        // per-lane base addresses (bytes)
        uint32_t a_base = A_u + (uint32_t)(wm*32 + lr)*144 + lh*16;
        uint32_t b_base = W_u + (uint32_t)(qk + (lane & 7))*528 + (uint32_t)(wn*64 + qn)*2;

        #pragma unroll
        for (int kk = 0; kk < 64; kk += 16) {
            uint32_t af[2][4];
            #pragma unroll
            for (int mi = 0; mi < 2; mi++)
                LDM4(af[mi], a_base + mi*(16*144) + kk*2);
            uint32_t bf[4][4];     // bf[j2] = {b0(n j2*2), b1(n j2*2), b0(n j2*2+1), b1(n j2*2+1)}
            #pragma unroll
            for (int j2 = 0; j2 < 4; j2++)
                LDM4T(bf[j2], b_base + (uint32_t)kk*528 + j2*32);
            #pragma unroll
            for (int mi = 0; mi < 2; mi++)
                #pragma unroll
                for (int j = 0; j < 8; j++)
                    MMA16816(acc[mi][j], af[mi],
                             bf[j>>1][(j&1)*2], bf[j>>1][(j&1)*2 + 1]);
        }
    }
    __syncthreads();   // all smem reads done before C_s overwrite

    // ---- dump accumulators to C_s [128][260] ----
    {
        int r0 = wm*32 + (lane >> 2);
        int c0 = wn*64 + (lane & 3)*2;
        #pragma unroll
        for (int mi = 0; mi < 2; mi++)
            #pragma unroll
            for (int j = 0; j < 8; j++) {
                float* p0 = C_s + (r0 + mi*16    )*260 + c0 + j*8;
                float* p1 = C_s + (r0 + mi*16 + 8)*260 + c0 + j*8;
                p0[0] = acc[mi][j][0]; p0[1] = acc[mi][j][1];
                p1[0] = acc[mi][j][2]; p1[1] = acc[mi][j][3];
            }
    }
    __syncthreads();

    // ---- epilogues (512 threads) ----
    if constexpr (MODE == 0) {
        const float scale = 0.125f;                 // R^-0.5
        int row  = t >> 2;                          // 128 rows
        int head = t & 3;                           // 4 head blocks of 64
        const float* rowp = C_s + row*260 + head*64;
        float m = -1e30f;
        #pragma unroll
        for (int j = 0; j < 64; j++) m = fmaxf(m, rowp[j] * scale);
        float s = 0.f;
        #pragma unroll
        for (int j = 0; j < 64; j++) s += __expf(rowp[j]*scale - m);
        float inv = 1.f / s;
        __half* op = g_P + (size_t)(row0 + row)*1024 + n0 + head*64;
        #pragma unroll
        for (int j = 0; j < 64; j += 8) {
            union { uint4 u4; __half2 h2[4]; } pk;
            #pragma unroll
            for (int qq = 0; qq < 4; qq++) {
                float v0 = __expf(rowp[j + 2*qq    ]*scale - m) * inv;
                float v1 = __expf(rowp[j + 2*qq + 1]*scale - m) * inv;
                pk.h2[qq] = __floats2half2_rn(v0, v1);
            }
            *(uint4*)(op + j) = pk.u4;
        }
    } else if constexpr (MODE == 1 || MODE == 2) {
        __half* dstbase = (MODE == 1) ? g_U : g_H;
        #pragma unroll
        for (int v = 0; v < 8; v++) {
            int lin = t + 512 * v;
            int i = lin >> 5, u = lin & 31;
            const float* src = C_s + i*260 + u*8;
            float vals[8];
            #pragma unroll
            for (int jj = 0; jj < 8; jj++) vals[jj] = src[jj];
            if constexpr (MODE == 2) {
                #pragma unroll
                for (int jj = 0; jj < 8; jj++) {
                    float z = vals[jj] + __ldg(bias + n0 + u*8 + jj);
                    vals[jj] = 0.5f * z * (1.0f + erff(z * 0.70710678118f));
                }
            }
            union { uint4 u4; __half2 h2[4]; } pk;
            #pragma unroll
            for (int qq = 0; qq < 4; qq++)
                pk.h2[qq] = __floats2half2_rn(vals[2*qq], vals[2*qq+1]);
            *(uint4*)(dstbase + (size_t)(row0 + i)*1024 + n0 + u*8) = pk.u4;
        }
    } else {
        // MODE 3: y = C + b2 + U residual; 512 threads = 256 cols x 2 row halves
        {
            int gcol = n0 + (t & 255);
            int half = t >> 8;                      // rows 0-63 / 64-127
            float b2v = __ldg(bias + gcol);
            float s = 0.f;
            int i0 = half*64;
            #pragma unroll 4
            for (int i = i0; i < i0 + 64; i++) {
                float u = __half2float(g_U[(size_t)(row0 + i)*1024 + gcol]);
                s += C_s[i*260 + (t & 255)] + b2v + u;
            }
            int b = row0 >> 12;
            atomicAdd(outp + b*1024 + gcol, s * (1.0f/4096.0f));
        }
    }
}

// ---------------- launch ----------------
extern "C" void kernel_launch(void* const* d_in, const int* in_sizes, int n_in,
                              void* d_out, int out_size) {
    const float* x  = (const float*)d_in[0];
    const float* wq = (const float*)d_in[1];
    const float* kv = (const float*)d_in[2];
    const float* wo = (const float*)d_in[3];
    const float* w1 = (const float*)d_in[4];
    const float* b1 = (const float*)d_in[5];
    const float* w2 = (const float*)d_in[6];
    const float* b2 = (const float*)d_in[7];
    float* out = (float*)d_out;

    cudaFuncSetAttribute(fused_gemm<0>, cudaFuncAttributeMaxDynamicSharedMemorySize, SMEM_BYTES);
    cudaFuncSetAttribute(fused_gemm<1>, cudaFuncAttributeMaxDynamicSharedMemorySize, SMEM_BYTES);
    cudaFuncSetAttribute(fused_gemm<2>, cudaFuncAttributeMaxDynamicSharedMemorySize, SMEM_BYTES);
    cudaFuncSetAttribute(fused_gemm<3>, cudaFuncAttributeMaxDynamicSharedMemorySize, SMEM_BYTES);

    // order: 4th launch is what ncu captures -> keep the GEMM there
    conv_x_kernel<<<65536, 256>>>(x);                              // 1
    prep_A_kernel<<<dim3(16, 16), 256>>>(wq, kv);                  // 2
    prep_B_kernel<<<dim3(16, 16), 256>>>(kv, wo);                  // 3
    fused_gemm<0><<<NBLOCKS, 512, SMEM_BYTES>>>(nullptr, nullptr); // 4 <- profiled
    conv_w_kernel<<<4096, 256>>>(w1, w2);                          // 5
    zero_out_kernel<<<128, 256>>>(out, BATCH * DIM);               // 6
    fused_gemm<1><<<NBLOCKS, 512, SMEM_BYTES>>>(nullptr, nullptr); // 7
    fused_gemm<2><<<NBLOCKS, 512, SMEM_BYTES>>>(b1,      nullptr); // 8
    fused_gemm<3><<<NBLOCKS, 512, SMEM_BYTES>>>(b2,      out);     // 9
}

// round 12
// speedup vs baseline: 1.2882x; 1.2392x over previous
#include <cuda_runtime.h>
#include <cuda_fp16.h>
#include <cstdint>

// Problem constants
#define NTOK   131072          // B*S = 32*4096
#define DIM    1024
#define BATCH  32
#define SEQ    4096
#define NBLOCKS ((NTOK/128)*(DIM/256))  // 4096

// ---------------- device scratch ----------------
__device__ __half g_A  [1024*1024];            // logits weights: wq_h @ kv_h^T  [d][hr]
__device__ __half g_Bm [1024*1024];            // kv_h @ wo_h                   [hr][d]
__device__ __half g_w1h[1024*1024];            // w1 [k][n]
__device__ __half g_Xh [(size_t)NTOK*1024];    // x in fp16     (256MB)
__device__ __half g_P  [(size_t)NTOK*1024];    // softmax probs (256MB)
__device__ __half g_U  [(size_t)NTOK*1024];    // out@wo        (256MB)
__device__ float  g_Usum[BATCH*DIM];           // column pools
__device__ float  g_Hsum[BATCH*DIM];

// ---------------- helpers ----------------
__device__ __forceinline__ uint32_t s2u(const void* p) {
    uint32_t a;
    asm("{ .reg .u64 t; cvta.to.shared.u64 t, %1; cvt.u32.u64 %0, t; }" : "=r"(a) : "l"(p));
    return a;
}
__device__ __forceinline__ void cpa16(void* dst, const void* src) {
    unsigned s = (unsigned)__cvta_generic_to_shared(dst);
    asm volatile("cp.async.cg.shared.global [%0], [%1], 16;\n" :: "r"(s), "l"(src));
}
#define LDM4(r, addr) \
    asm volatile("ldmatrix.sync.aligned.m8n8.x4.shared.b16 {%0,%1,%2,%3}, [%4];" \
        : "=r"((r)[0]), "=r"((r)[1]), "=r"((r)[2]), "=r"((r)[3]) : "r"(addr))
#define LDM4T(r, addr) \
    asm volatile("ldmatrix.sync.aligned.m8n8.x4.trans.shared.b16 {%0,%1,%2,%3}, [%4];" \
        : "=r"((r)[0]), "=r"((r)[1]), "=r"((r)[2]), "=r"((r)[3]) : "r"(addr))
#define MMA16816(d, a, b0v, b1v) \
    asm volatile("mma.sync.aligned.m16n8k16.row.col.f32.f16.f16.f32 " \
        "{%0,%1,%2,%3}, {%4,%5,%6,%7}, {%8,%9}, {%0,%1,%2,%3};" \
        : "+f"((d)[0]), "+f"((d)[1]), "+f"((d)[2]), "+f"((d)[3]) \
        : "r"((a)[0]), "r"((a)[1]), "r"((a)[2]), "r"((a)[3]), "r"(b0v), "r"(b1v))

// ---------------- prep kernels (hardware-validated) ----------------
__global__ void zero_sums_kernel() {
    int i = blockIdx.x * 256 + threadIdx.x;    // grid covers 32768
    g_Usum[i] = 0.f;
    g_Hsum[i] = 0.f;
}

__global__ void prep_A_kernel(const float* __restrict__ wq,
                              const float* __restrict__ kv) {
    __shared__ float wq_s[64][65];
    __shared__ float kv_s[64][65];
    int h  = blockIdx.x;
    int dt = blockIdx.y;
    int t  = threadIdx.x;
    #pragma unroll
    for (int e = 0; e < 16; e++) {
        int lin = t + 256 * e;
        int r = lin >> 6, c = lin & 63;
        wq_s[r][c] = wq[(size_t)(dt*64 + r)*1024 + h*64 + c];
        kv_s[r][c] = kv[(size_t)r*1024 + h*64 + c];
    }
    __syncthreads();
    #pragma unroll
    for (int e = 0; e < 16; e++) {
        int lin = t + 256 * e;
        int i = lin >> 6, r = lin & 63;
        float s = 0.f;
        #pragma unroll
        for (int j = 0; j < 64; j++) s += wq_s[i][j] * kv_s[r][j];
        g_A[(size_t)(dt*64 + i)*1024 + h*64 + r] = __float2half_rn(s);
    }
}

__global__ void prep_B_kernel(const float* __restrict__ kv,
                              const float* __restrict__ wo) {
    __shared__ float kv_s[64][65];
    __shared__ float wo_s[64][65];
    int h  = blockIdx.x;
    int ct = blockIdx.y;
    int t  = threadIdx.x;
    #pragma unroll
    for (int e = 0; e < 16; e++) {
        int lin = t + 256 * e;
        int r = lin >> 6, c = lin & 63;
        kv_s[r][c] = kv[(size_t)r*1024 + h*64 + c];
        wo_s[r][c] = wo[(size_t)(h*64 + r)*1024 + ct*64 + c];
    }
    __syncthreads();
    #pragma unroll
    for (int e = 0; e < 16; e++) {
        int lin = t + 256 * e;
        int r = lin >> 6, d = lin & 63;
        float s = 0.f;
        #pragma unroll
        for (int j = 0; j < 64; j++) s += kv_s[r][j] * wo_s[j][d];
        g_Bm[(size_t)(h*64 + r)*1024 + ct*64 + d] = __float2half_rn(s);
    }
}

__global__ void conv_w_kernel(const float* __restrict__ w1) {
    int i = blockIdx.x * 256 + threadIdx.x;
    g_w1h[i] = __float2half_rn(w1[i]);
}

__global__ void conv_x_kernel(const float* __restrict__ x) {
    size_t i = ((size_t)blockIdx.x * 256 + threadIdx.x) * 8;
    float4 a = *(const float4*)(x + i);
    float4 b = *(const float4*)(x + i + 4);
    union { uint4 u4; __half2 h2[4]; } pk;
    pk.h2[0] = __floats2half2_rn(a.x, a.y);
    pk.h2[1] = __floats2half2_rn(a.z, a.w);
    pk.h2[2] = __floats2half2_rn(b.x, b.y);
    pk.h2[3] = __floats2half2_rn(b.z, b.w);
    *(uint4*)(g_Xh + i) = pk.u4;
}

// final: out[b][col] = (Hsum[b]/4096) @ w2[:,col] + b2[col] + Usum[b][col]/4096
__global__ void final_kernel(const float* __restrict__ w2,
                             const float* __restrict__ b2,
                             float* __restrict__ outp) {
    __shared__ float hs[1024];
    int b  = blockIdx.x;
    int cc = blockIdx.y;
    int t  = threadIdx.x;
    int col = cc*128 + t;
    #pragma unroll
    for (int e = 0; e < 8; e++)
        hs[t + 128*e] = g_Hsum[b*1024 + t + 128*e];
    __syncthreads();
    float s = 0.f;
    #pragma unroll 4
    for (int k = 0; k < 1024; k++)
        s += hs[k] * __ldg(w2 + (size_t)k*1024 + col);
    outp[b*1024 + col] = s * (1.0f/4096.0f) + __ldg(b2 + col)
                       + g_Usum[b*1024 + col] * (1.0f/4096.0f);
}

// ---- fused GEMM: 128x256 tile, 512 threads, chunk 64, 3-stage cp.async,
// ---- raw ldmatrix + mma.sync.m16n8k16 inner loop.  MODES 0..2 only.
#define A_BYTES     18432
#define STAGE_BYTES 52224
#define SMEM_BYTES  (3*STAGE_BYTES)

template<int MODE>
__global__ void __launch_bounds__(512)
fused_gemm(const float* __restrict__ bias) {
    extern __shared__ char smem[];
    uint32_t sbase = s2u(smem);
    float* C_s = (float*)smem;     // 128 x 260 floats (reuse)

    const __half* Ag;
    const __half* Wg;
    if constexpr (MODE == 0)      { Ag = g_Xh; Wg = g_A;   }
    else if constexpr (MODE == 1) { Ag = g_P;  Wg = g_Bm;  }
    else                          { Ag = g_U;  Wg = g_w1h; }

    int t    = threadIdx.x;
    int bid  = blockIdx.x;
    int rt   = bid >> 2;       // 1024 row tiles
    int ct   = bid & 3;        // 4 col tiles of 256
    int row0 = rt * 128;
    int n0   = ct * 256;
    int warp = t >> 5;
    int lane = t & 31;
    int wm   = warp & 3;       // 4 warp rows of 32
    int wn   = warp >> 2;      // 4 warp cols of 64

    int lr = lane & 15, lh = lane >> 4;       // A: row lr, k-half lh
    int q  = lane >> 3;                       // B: quad 0..3
    int qk = (q & 1) * 8;
    int qn = (q >> 1) * 8;

    float acc[2][8][4];
    #pragma unroll
    for (int mi = 0; mi < 2; mi++)
        #pragma unroll
        for (int j = 0; j < 8; j++)
            #pragma unroll
            for (int c = 0; c < 4; c++) acc[mi][j][c] = 0.f;

    auto stage = [&](int kc, int buf) {
        __half* A_s = (__half*)(smem + buf*STAGE_BYTES);
        __half* W_s = (__half*)(smem + buf*STAGE_BYTES + A_BYTES);
        #pragma unroll
        for (int e = 0; e < 2; e++) {            // A: 128 x 64
            int lin = t + 512*e;
            int r = lin >> 3, sg = lin & 7;
            cpa16(A_s + r*72 + sg*8, Ag + (size_t)(row0 + r)*1024 + kc + sg*8);
        }
        #pragma unroll
        for (int e = 0; e < 4; e++) {            // W: 64 x 256
            int lin = t + 512*e;
            int r = lin >> 5, sg = lin & 31;
            cpa16(W_s + r*264 + sg*8, Wg + (size_t)(kc + r)*1024 + n0 + sg*8);
        }
        asm volatile("cp.async.commit_group;\n");
    };

    stage(0, 0);
    stage(64, 1);

    for (int k = 0; k < 16; k++) {
        if (k < 15) asm volatile("cp.async.wait_group 1;\n");
        else        asm volatile("cp.async.wait_group 0;\n");
        __syncthreads();

        if (k + 2 < 16) stage((k+2)*64, (k+2) % 3);

        int slot = k - (k/3)*3;
        uint32_t A_u = sbase + slot*STAGE_BYTES;
        uint32_t W_u = A_u + A_BYTES;
        uint32_t a_base = A_u + (uint32_t)(wm*32 + lr)*144 + lh*16;
        uint32_t b_base = W_u + (uint32_t)(qk + (lane & 7))*528 + (uint32_t)(wn*64 + qn)*2;

        #pragma unroll
        for (int kk = 0; kk < 64; kk += 16) {
            uint32_t af[2][4];
            #pragma unroll
            for (int mi = 0; mi < 2; mi++)
                LDM4(af[mi], a_base + mi*(16*144) + kk*2);
            uint32_t bf[4][4];
            #pragma unroll
            for (int j2 = 0; j2 < 4; j2++)
                LDM4T(bf[j2], b_base + (uint32_t)kk*528 + j2*32);
            #pragma unroll
            for (int mi = 0; mi < 2; mi++)
                #pragma unroll
                for (int j = 0; j < 8; j++)
                    MMA16816(acc[mi][j], af[mi],
                             bf[j>>1][(j&1)*2], bf[j>>1][(j&1)*2 + 1]);
        }
    }
    __syncthreads();   // all smem reads done before C_s overwrite

    // ---- dump accumulators to C_s [128][260] ----
    {
        int r0 = wm*32 + (lane >> 2);
        int c0 = wn*64 + (lane & 3)*2;
        #pragma unroll
        for (int mi = 0; mi < 2; mi++)
            #pragma unroll
            for (int j = 0; j < 8; j++) {
                float* p0 = C_s + (r0 + mi*16    )*260 + c0 + j*8;
                float* p1 = C_s + (r0 + mi*16 + 8)*260 + c0 + j*8;
                p0[0] = acc[mi][j][0]; p0[1] = acc[mi][j][1];
                p1[0] = acc[mi][j][2]; p1[1] = acc[mi][j][3];
            }
    }
    __syncthreads();

    // ---- epilogues (512 threads) ----
    if constexpr (MODE == 0) {
        const float scale = 0.125f;                 // R^-0.5
        int row  = t >> 2;
        int head = t & 3;
        const float* rowp = C_s + row*260 + head*64;
        float m = -1e30f;
        #pragma unroll
        for (int j = 0; j < 64; j++) m = fmaxf(m, rowp[j] * scale);
        float s = 0.f;
        #pragma unroll
        for (int j = 0; j < 64; j++) s += __expf(rowp[j]*scale - m);
        float inv = 1.f / s;
        __half* op = g_P + (size_t)(row0 + row)*1024 + n0 + head*64;
        #pragma unroll
        for (int j = 0; j < 64; j += 8) {
            union { uint4 u4; __half2 h2[4]; } pk;
            #pragma unroll
            for (int qq = 0; qq < 4; qq++) {
                float v0 = __expf(rowp[j + 2*qq    ]*scale - m) * inv;
                float v1 = __expf(rowp[j + 2*qq + 1]*scale - m) * inv;
                pk.h2[qq] = __floats2half2_rn(v0, v1);
            }
            *(uint4*)(op + j) = pk.u4;
        }
    } else if constexpr (MODE == 1) {
        // store U (fp16) + column-pool U into g_Usum
        #pragma unroll
        for (int v = 0; v < 8; v++) {
            int lin = t + 512 * v;
            int i = lin >> 5, u = lin & 31;
            const float* src = C_s + i*260 + u*8;
            union { uint4 u4; __half2 h2[4]; } pk;
            #pragma unroll
            for (int qq = 0; qq < 4; qq++)
                pk.h2[qq] = __floats2half2_rn(src[2*qq], src[2*qq+1]);
            *(uint4*)(g_U + (size_t)(row0 + i)*1024 + n0 + u*8) = pk.u4;
        }
        // pool (C_s untouched)
        {
            int col  = t & 255;
            int half = t >> 8;
            float s = 0.f;
            int i0 = half*64;
            #pragma unroll 4
            for (int i = i0; i < i0 + 64; i++) s += C_s[i*260 + col];
            int b = row0 >> 12;
            atomicAdd(g_Usum + b*1024 + n0 + col, s);
        }
    } else {
        // MODE 2: gelu(C + b1) -> column-pool into g_Hsum (no store of H)
        #pragma unroll
        for (int v = 0; v < 8; v++) {
            int lin = t + 512 * v;
            int i = lin >> 5, u = lin & 31;
            float* src = C_s + i*260 + u*8;
            #pragma unroll
            for (int jj = 0; jj < 8; jj++) {
                float z = src[jj] + __ldg(bias + n0 + u*8 + jj);
                src[jj] = 0.5f * z * (1.0f + erff(z * 0.70710678118f));
            }
        }
        __syncthreads();
        {
            int col  = t & 255;
            int half = t >> 8;
            float s = 0.f;
            int i0 = half*64;
            #pragma unroll 4
            for (int i = i0; i < i0 + 64; i++) s += C_s[i*260 + col];
            int b = row0 >> 12;
            atomicAdd(g_Hsum + b*1024 + n0 + col, s);
        }
    }
}

// ---------------- launch ----------------
extern "C" void kernel_launch(void* const* d_in, const int* in_sizes, int n_in,
                              void* d_out, int out_size) {
    const float* x  = (const float*)d_in[0];
    const float* wq = (const float*)d_in[1];
    const float* kv = (const float*)d_in[2];
    const float* wo = (const float*)d_in[3];
    const float* w1 = (const float*)d_in[4];
    const float* b1 = (const float*)d_in[5];
    const float* w2 = (const float*)d_in[6];
    const float* b2 = (const float*)d_in[7];
    float* out = (float*)d_out;

    cudaFuncSetAttribute(fused_gemm<0>, cudaFuncAttributeMaxDynamicSharedMemorySize, SMEM_BYTES);
    cudaFuncSetAttribute(fused_gemm<1>, cudaFuncAttributeMaxDynamicSharedMemorySize, SMEM_BYTES);
    cudaFuncSetAttribute(fused_gemm<2>, cudaFuncAttributeMaxDynamicSharedMemorySize, SMEM_BYTES);

    // order: 4th launch is what ncu captures -> keep the GEMM there
    conv_x_kernel<<<65536, 256>>>(x);                              // 1
    prep_A_kernel<<<dim3(16, 16), 256>>>(wq, kv);                  // 2
    prep_B_kernel<<<dim3(16, 16), 256>>>(kv, wo);                  // 3
    fused_gemm<0><<<NBLOCKS, 512, SMEM_BYTES>>>(nullptr);          // 4 <- profiled
    conv_w_kernel<<<4096, 256>>>(w1);                              // 5
    zero_sums_kernel<<<128, 256>>>();                              // 6
    fused_gemm<1><<<NBLOCKS, 512, SMEM_BYTES>>>(nullptr);          // 7
    fused_gemm<2><<<NBLOCKS, 512, SMEM_BYTES>>>(b1);               // 8
    final_kernel<<<dim3(32, 8), 128>>>(w2, b2, out);               // 9
}